// round 3
// baseline (speedup 1.0000x reference)
#include <cuda_runtime.h>

// Problem constants
#define B_  2
#define S_  2048
#define DM  768
#define H_  12
#define DK  64

// Scratch (allocation-free rule: device globals)
__device__ float g_Q[B_ * S_ * DM];
__device__ float g_K[B_ * S_ * DM];
__device__ float g_V[B_ * S_ * DM];
__device__ float g_X[B_ * S_ * DM];

// ---------------------------------------------------------------------------
// GEMM: C[M,N] = A[M,K] @ W[N,K]^T + bias[N]
// 128x128 tile, BK=8, 256 threads, 8x8 microtile, double-buffered smem.
// ---------------------------------------------------------------------------
__global__ __launch_bounds__(256) void gemm_nt_bias(
    const float* __restrict__ A, const float* __restrict__ W,
    const float* __restrict__ bias, float* __restrict__ C,
    int M, int N, int K)
{
    __shared__ float As[2][8][128];
    __shared__ float Ws[2][8][128];

    const int t  = threadIdx.x;
    const int tx = t & 15;        // N microtile
    const int ty = t >> 4;        // M microtile
    const int bm = blockIdx.y * 128;
    const int bn = blockIdx.x * 128;

    const int lrow = t >> 1;        // 0..127
    const int lk   = (t & 1) * 4;   // 0 or 4

    float acc[8][8];
#pragma unroll
    for (int i = 0; i < 8; i++)
#pragma unroll
        for (int j = 0; j < 8; j++) acc[i][j] = 0.f;

    const float* Aptr = A + (size_t)(bm + lrow) * K + lk;
    const float* Wptr = W + (size_t)(bn + lrow) * K + lk;

    // preload tile 0
    {
        float4 av = *(const float4*)(Aptr);
        float4 wv = *(const float4*)(Wptr);
        As[0][lk + 0][lrow] = av.x; As[0][lk + 1][lrow] = av.y;
        As[0][lk + 2][lrow] = av.z; As[0][lk + 3][lrow] = av.w;
        Ws[0][lk + 0][lrow] = wv.x; Ws[0][lk + 1][lrow] = wv.y;
        Ws[0][lk + 2][lrow] = wv.z; Ws[0][lk + 3][lrow] = wv.w;
    }
    __syncthreads();

    int cur = 0;
    for (int kt = 0; kt < K; kt += 8) {
        const bool has_next = (kt + 8) < K;
        float4 av2, wv2;
        if (has_next) {
            av2 = *(const float4*)(Aptr + kt + 8);
            wv2 = *(const float4*)(Wptr + kt + 8);
        }

#pragma unroll
        for (int k = 0; k < 8; k++) {
            float a[8], b[8];
            *(float4*)&a[0] = *(const float4*)&As[cur][k][ty * 8 + 0];
            *(float4*)&a[4] = *(const float4*)&As[cur][k][ty * 8 + 4];
            *(float4*)&b[0] = *(const float4*)&Ws[cur][k][tx * 8 + 0];
            *(float4*)&b[4] = *(const float4*)&Ws[cur][k][tx * 8 + 4];
#pragma unroll
            for (int i = 0; i < 8; i++)
#pragma unroll
                for (int j = 0; j < 8; j++)
                    acc[i][j] = fmaf(a[i], b[j], acc[i][j]);
        }

        if (has_next) {
            const int nxt = cur ^ 1;
            As[nxt][lk + 0][lrow] = av2.x; As[nxt][lk + 1][lrow] = av2.y;
            As[nxt][lk + 2][lrow] = av2.z; As[nxt][lk + 3][lrow] = av2.w;
            Ws[nxt][lk + 0][lrow] = wv2.x; Ws[nxt][lk + 1][lrow] = wv2.y;
            Ws[nxt][lk + 2][lrow] = wv2.z; Ws[nxt][lk + 3][lrow] = wv2.w;
        }
        __syncthreads();
        cur ^= 1;
    }

    float bv[8];
#pragma unroll
    for (int j = 0; j < 8; j++) bv[j] = bias[bn + tx * 8 + j];

#pragma unroll
    for (int i = 0; i < 8; i++) {
        float* crow = C + (size_t)(bm + ty * 8 + i) * N + bn + tx * 8;
        float4 o0 = { acc[i][0] + bv[0], acc[i][1] + bv[1],
                      acc[i][2] + bv[2], acc[i][3] + bv[3] };
        float4 o1 = { acc[i][4] + bv[4], acc[i][5] + bv[5],
                      acc[i][6] + bv[6], acc[i][7] + bv[7] };
        *(float4*)(crow + 0) = o0;
        *(float4*)(crow + 4) = o1;
    }
}

// ---------------------------------------------------------------------------
// Causal flash attention v2: chunked softmax for ILP.
// One thread per query row, 128 queries/block. K/V staged in smem 64 keys at
// a time; processed in half-chunks of 32 keys: 32 independent score chains,
// one max + one o-rescale + 32 pipelined exps per half-chunk.
// ---------------------------------------------------------------------------
template<bool MASKED>
__device__ __forceinline__ void process_half(
    const float4* __restrict__ kk,   // &Ks4[jb*16]
    const float4* __restrict__ vv,   // &Vs4[jb*16]
    const float4* __restrict__ q4,   // q in registers (array of 16 float4)
    float4* __restrict__ o4,
    float& m, float& l, int rel_end) // keys valid: j < rel_end (MASKED only)
{
    float s[32];
#pragma unroll
    for (int j = 0; j < 32; j++) s[j] = 0.f;

    // Scores: d4-outer, j-inner -> 32 independent accumulator chains.
#pragma unroll
    for (int d4 = 0; d4 < 16; d4++) {
        const float4 qa = q4[d4];
#pragma unroll
        for (int j = 0; j < 32; j++) {
            const float4 kv = kk[j * 16 + d4];
            s[j] = fmaf(qa.x, kv.x, s[j]);
            s[j] = fmaf(qa.y, kv.y, s[j]);
            s[j] = fmaf(qa.z, kv.z, s[j]);
            s[j] = fmaf(qa.w, kv.w, s[j]);
        }
    }

    float cmax = -1e30f;
#pragma unroll
    for (int j = 0; j < 32; j++) {
        float sj = s[j] * 0.125f;               // 1/sqrt(64)
        if (MASKED) { if (j >= rel_end) sj = -1e30f; }
        s[j] = sj;
        cmax = fmaxf(cmax, sj);
    }

    const float newm = fmaxf(m, cmax);
    const float corr = __expf(m - newm);        // 0 on first chunk
    m = newm;
    l *= corr;
#pragma unroll
    for (int d4 = 0; d4 < 16; d4++) {
        o4[d4].x *= corr; o4[d4].y *= corr;
        o4[d4].z *= corr; o4[d4].w *= corr;
    }

    float p[32];
    float lsum = 0.f;
#pragma unroll
    for (int j = 0; j < 32; j++) {
        p[j] = __expf(s[j] - newm);             // masked -> exp(-huge)=0
        lsum += p[j];
    }
    l += lsum;

    // PV: j-outer, d4-inner -> o reuse distance = 80 instructions.
#pragma unroll
    for (int j = 0; j < 32; j++) {
        const float pj = p[j];
#pragma unroll
        for (int d4 = 0; d4 < 16; d4++) {
            const float4 v4 = vv[j * 16 + d4];
            o4[d4].x = fmaf(pj, v4.x, o4[d4].x);
            o4[d4].y = fmaf(pj, v4.y, o4[d4].y);
            o4[d4].z = fmaf(pj, v4.z, o4[d4].z);
            o4[d4].w = fmaf(pj, v4.w, o4[d4].w);
        }
    }
}

__global__ __launch_bounds__(128) void attn_kernel(
    const float* __restrict__ Q, const float* __restrict__ K,
    const float* __restrict__ V, float* __restrict__ X)
{
    __shared__ float4 Ks4[64 * 16];
    __shared__ float4 Vs4[64 * 16];

    const int tid = threadIdx.x;
    const int h   = blockIdx.y;
    const int b   = blockIdx.z;
    // Reverse x so heaviest (most-keys) blocks launch first (LPT).
    const int qblk = (int)gridDim.x - 1 - (int)blockIdx.x;
    const int q0   = qblk * 128;
    const int qi   = q0 + tid;

    float4 q4[16];
    {
        const float4* qptr = (const float4*)(Q + ((size_t)(b * S_ + qi)) * DM + h * DK);
#pragma unroll
        for (int d4 = 0; d4 < 16; d4++) q4[d4] = qptr[d4];
    }

    float4 o4[16];
#pragma unroll
    for (int d4 = 0; d4 < 16; d4++) o4[d4] = make_float4(0.f, 0.f, 0.f, 0.f);
    float m = -1e30f, l = 0.f;

    const int kmax = q0 + 128;

    for (int c0 = 0; c0 < kmax; c0 += 64) {
        // Stage 64 keys of K and V (coalesced, 16 float4/row).
        const float4* kb4 = (const float4*)(K + ((size_t)(b * S_ + c0)) * DM + h * DK);
        const float4* vb4 = (const float4*)(V + ((size_t)(b * S_ + c0)) * DM + h * DK);
#pragma unroll
        for (int i = 0; i < 8; i++) {
            const int idx = tid + i * 128;        // 0..1023
            const int j   = idx >> 4;
            const int cc  = idx & 15;
            Ks4[idx] = kb4[(size_t)j * (DM / 4) + cc];
            Vs4[idx] = vb4[(size_t)j * (DM / 4) + cc];
        }
        __syncthreads();

        int jend = qi - c0 + 1;
        if (jend > 64) jend = 64;

        if (jend >= 64) {
            process_half<false>(Ks4,            Vs4,            q4, o4, m, l, 32);
            process_half<false>(Ks4 + 32 * 16,  Vs4 + 32 * 16,  q4, o4, m, l, 32);
        } else if (jend > 32) {
            process_half<false>(Ks4,            Vs4,            q4, o4, m, l, 32);
            process_half<true>( Ks4 + 32 * 16,  Vs4 + 32 * 16,  q4, o4, m, l, jend - 32);
        } else if (jend > 0) {
            process_half<true>( Ks4,            Vs4,            q4, o4, m, l, jend);
        }
        __syncthreads();
    }

    const float inv = 1.f / l;
    float4* xptr = (float4*)(X + ((size_t)(b * S_ + qi)) * DM + h * DK);
#pragma unroll
    for (int d4 = 0; d4 < 16; d4++) {
        float4 ov = { o4[d4].x * inv, o4[d4].y * inv,
                      o4[d4].z * inv, o4[d4].w * inv };
        xptr[d4] = ov;
    }
}

// ---------------------------------------------------------------------------
// Launch
// Inputs: 0:q 1:k 2:v 3:mask 4:wq 5:bq 6:wk 7:bk 8:wv 9:bv 10:wo 11:bo
// ---------------------------------------------------------------------------
extern "C" void kernel_launch(void* const* d_in, const int* in_sizes, int n_in,
                              void* d_out, int out_size)
{
    const float* q  = (const float*)d_in[0];
    const float* k  = (const float*)d_in[1];
    const float* v  = (const float*)d_in[2];
    const float* wq = (const float*)d_in[4];
    const float* bq = (const float*)d_in[5];
    const float* wk = (const float*)d_in[6];
    const float* bk = (const float*)d_in[7];
    const float* wv = (const float*)d_in[8];
    const float* bv = (const float*)d_in[9];
    const float* wo = (const float*)d_in[10];
    const float* bo = (const float*)d_in[11];
    float* out = (float*)d_out;

    float *gQ, *gK, *gV, *gX;
    cudaGetSymbolAddress((void**)&gQ, g_Q);
    cudaGetSymbolAddress((void**)&gK, g_K);
    cudaGetSymbolAddress((void**)&gV, g_V);
    cudaGetSymbolAddress((void**)&gX, g_X);

    const int M = B_ * S_;  // 4096
    dim3 ggrid(DM / 128, M / 128);   // (6, 32)
    dim3 gblk(256);

    gemm_nt_bias<<<ggrid, gblk>>>(q, wq, bq, gQ, M, DM, DM);
    gemm_nt_bias<<<ggrid, gblk>>>(k, wk, bk, gK, M, DM, DM);
    gemm_nt_bias<<<ggrid, gblk>>>(v, wv, bv, gV, M, DM, DM);

    dim3 agrid(S_ / 128, H_, B_);    // (16, 12, 2)
    attn_kernel<<<agrid, 128>>>(gQ, gK, gV, gX);

    gemm_nt_bias<<<ggrid, gblk>>>(gX, wo, bo, out, M, DM, DM);
}